// round 7
// baseline (speedup 1.0000x reference)
#include <cuda_runtime.h>
#include <cuda_bf16.h>

// Problem constants
#define NSPL 191               // 3*64 - 1 spline dims
#define KB   64                // bins

// smem layout: per row, 16 chunks of 8 floats; chunk c at float-offset c*12
// (stride 12 makes lane start-banks 12s mod 32 all distinct -> conflict-free LDS.128)
#define ROWF 192               // floats per smem row (16 chunks * 12)

__device__ __forceinline__ float softplus_f(float x) {
    return fmaxf(x, 0.0f) + __logf(1.0f + __expf(-fabsf(x)));
}

// 4 cuts per warp: lane = 8*g + s; group g handles cut warp*4+g,
// sublane s owns bins [8s, 8s+8). Block = 256 threads = 32 cuts.
__global__ __launch_bounds__(256)
void rqs_logdet4s_kernel(const float* __restrict__ value,
                         const float* __restrict__ delta_spline,
                         const int*   __restrict__ genes_oi,
                         const int*   __restrict__ local_gene_ix,
                         const float* __restrict__ spline_weight,
                         float*       __restrict__ out,
                         int n)
{
    const unsigned FULL = 0xffffffffu;
    const float WINDOW_A      = -10000.0f;
    const float INV_AB        = 1.0f / 20000.0f;
    const float MBW           = 0.001f;
    const float MBH           = 0.001f;
    const float MDER          = 0.001f;
    const float DEFAULT_INIT  = 0.53974366f;                 // log(exp(0.999)-1)
    const float OUT_CONST     = -0.69314718f - 9.90348755f;  // LOG_HALF - LOG_AB
    const float cH            = 1.0f - MBH * KB;             // 0.936
    const float cW            = 1.0f - MBW * KB;

    __shared__ __align__(16) float su[32 * ROWF];   // fused ds+sw, w|h regions
    __shared__ const float* swp[32];                // gene row pointers

    const int tid  = threadIdx.x;
    const long long cb = (long long)blockIdx.x * 32;  // block's first cut

    // ---- stage gene row pointers ----
    if (tid < 32) {
        long long cc = cb + tid;
        if (cc >= n) cc = n - 1;
        int gene = genes_oi[local_gene_ix[cc]];
        swp[tid] = spline_weight + (long long)gene * NSPL;
    }
    __syncthreads();

    // ---- stage fused (ds+sw) for cols [0,128) of each of 32 rows ----
    // e = row*128 + col; warps cover 32 consecutive cols of one row -> coalesced
    #pragma unroll
    for (int it = 0; it < 16; ++it) {
        int e   = tid + it * 256;
        int row = e >> 7;
        int col = e & 127;
        long long cc = cb + row;
        if (cc >= n) cc = n - 1;
        float v = delta_spline[cc * NSPL + col] + swp[row][col];
        su[row * ROWF + (col >> 3) * 12 + (col & 7)] = v;
    }
    __syncthreads();

    // ---- per-cut compute ----
    const int lane = tid & 31;
    const int g    = lane >> 3;
    const int s    = lane & 7;
    const int r    = ((tid >> 5) << 2) + g;        // smem row for this group
    long long cutl = cb + r;
    bool active = (cutl < n);
    int cut = active ? (int)cutl : (n - 1);

    // vector loads of this lane's 8 w-values and 8 h-values (conflict-free)
    const float4* wp = reinterpret_cast<const float4*>(&su[r * ROWF + s * 12]);
    float4 wa = wp[0], wb = wp[1];
    const float4* hp = reinterpret_cast<const float4*>(&su[r * ROWF + 96 + s * 12]);
    float4 ha = hp[0], hb = hp[1];

    float uwv[8] = {wa.x, wa.y, wa.z, wa.w, wb.x, wb.y, wb.z, wb.w};
    float uhv[8] = {ha.x, ha.y, ha.z, ha.w, hb.x, hb.y, hb.z, hb.w};

    float cum[8];
    float Swl = 0.0f, run = 0.0f;
    #pragma unroll
    for (int k = 0; k < 8; ++k) {
        Swl += __expf(uwv[k]);
        run += __expf(uhv[k]);
        cum[k] = run;
    }

    // width-8 exclusive scan of lane h-totals
    float incl = run;
    #pragma unroll
    for (int o = 1; o < 8; o <<= 1) {
        float u = __shfl_up_sync(FULL, incl, o, 8);
        if (s >= o) incl += u;
    }
    float excl = incl - run;
    float Sh = __shfl_sync(FULL, incl, 7, 8);
    #pragma unroll
    for (int k = 0; k < 8; ++k) cum[k] += excl;

    // widths total
    #pragma unroll
    for (int o = 4; o; o >>= 1) Swl += __shfl_xor_sync(FULL, Swl, o, 8);

    // ---- x ----
    float v  = value[cut];
    float x  = ((v - WINDOW_A) * INV_AB - 0.5f) * 2.0f;
    bool inside = (x >= -1.0f) && (x <= 1.0f);
    float xc = fminf(fmaxf(x, -1.0f), 1.0f);

    // ---- bin search ----
    float invSh = __fdividef(1.0f, Sh);
    float ShocH = Sh * (1.0f / cH);
    float stepl = MBH * ShocH;
    float R = (fmaf(xc, 0.5f, 0.5f) - (float)(s * 8 + 1) * MBH) * ShocH;
    int cnt = 0;
    #pragma unroll
    for (int k = 0; k < 8; ++k) {
        cnt += (cum[k] <= R);
        R -= stepl;
    }
    #pragma unroll
    for (int o = 4; o; o >>= 1) cnt += __shfl_xor_sync(FULL, cnt, o, 8);
    int idx = min(cnt, 63);                        // group-uniform

    // ---- gather cum[idx-1] via 8-way register tree + width-8 shfl ----
    int p  = idx - 1;
    int r2 = p & 7;
    int sl2 = (p >= 0) ? (p >> 3) : 0;
    float a01 = (r2 & 1) ? cum[1] : cum[0];
    float a23 = (r2 & 1) ? cum[3] : cum[2];
    float a45 = (r2 & 1) ? cum[5] : cum[4];
    float a67 = (r2 & 1) ? cum[7] : cum[6];
    float b0  = (r2 & 2) ? a23 : a01;
    float b1  = (r2 & 2) ? a67 : a45;
    float csel = (r2 & 4) ? b1 : b0;
    float c0 = __shfl_sync(FULL, csel, sl2, 8);
    if (idx == 0) c0 = 0.0f;

    // ---- values at idx from smem (group-uniform address) ----
    int co = (idx >> 3) * 12 + (idx & 7);
    float ew_g = __expf(su[r * ROWF + co]);
    float eh_g = __expf(su[r * ROWF + 96 + co]);

    // ---- derivatives: 2 scattered global loads (ud never streamed) ----
    const float* ds = delta_spline + (long long)cut * NSPL;
    const float* sw = swp[r];
    int i0 = max(idx - 1, 0);
    int i1 = min(idx, 62);
    float u0 = ds[2 * KB + i0] + sw[2 * KB + i0];
    float u1 = ds[2 * KB + i1] + sw[2 * KB + i1];
    if (idx == 0)  u0 = DEFAULT_INIT;
    if (idx == 63) u1 = DEFAULT_INIT;
    float d0 = MDER + softplus_f(u0);
    float d1 = MDER + softplus_f(u1);

    // ---- spline quantities at idx ----
    float h_sm = fmaf(cH * invSh, eh_g, MBH);
    float w_sm = fmaf(cW, __fdividef(ew_g, Swl), MBW);
    float in_h = 2.0f * h_sm;
    float dlt  = __fdividef(h_sm, w_sm);
    float in_ch = fmaf(2.0f, fmaf(cH * invSh, c0, (float)idx * MBH), -1.0f);

    // ---- rational-quadratic inverse, logabsdet only ----
    float dy = xc - in_ch;
    float sc = d0 + d1 - 2.0f * dlt;
    float a  = dy * sc + in_h * (dlt - d0);
    float b  = in_h * d0 - dy * sc;
    float c  = -dlt * dy;
    float disc = b * b - 4.0f * a * c;
    float root = __fdividef(2.0f * c, -b - sqrtf(fmaxf(disc, 0.0f)));
    float tom  = root * (1.0f - root);
    float denom = dlt + sc * tom;
    float omr  = 1.0f - root;
    float deriv_num = dlt * dlt * (d1 * root * root + 2.0f * dlt * tom + d0 * omr * omr);
    float logabsdet = -(__logf(deriv_num) - 2.0f * __logf(denom));

    float res = OUT_CONST + (inside ? logabsdet : 0.0f);
    if (s == 0 && active) out[cut] = res;
}

extern "C" void kernel_launch(void* const* d_in, const int* in_sizes, int n_in,
                              void* d_out, int out_size) {
    const float* value         = (const float*)d_in[0];
    const float* delta_spline  = (const float*)d_in[1];
    const int*   genes_oi      = (const int*)d_in[2];
    const int*   local_gene_ix = (const int*)d_in[3];
    const float* spline_weight = (const float*)d_in[4];
    float* out = (float*)d_out;
    int n = in_sizes[0];                      // N_CUTS
    int blocks = (n + 31) / 32;               // 32 cuts per 256-thread block
    rqs_logdet4s_kernel<<<blocks, 256>>>(value, delta_spline, genes_oi,
                                         local_gene_ix, spline_weight, out, n);
}

// round 8
// speedup vs baseline: 1.5856x; 1.5856x over previous
#include <cuda_runtime.h>
#include <cuda_bf16.h>

// Problem constants
#define NSPL 191               // 3*64 - 1 spline dims
#define KB   64                // bins

__device__ __forceinline__ float softplus_f(float x) {
    return fmaxf(x, 0.0f) + __logf(1.0f + __expf(-fabsf(x)));
}

// 8-way register select by uniform index k (0..7)
__device__ __forceinline__ float sel8(const float a[8], int k) {
    float x01 = (k & 1) ? a[1] : a[0];
    float x23 = (k & 1) ? a[3] : a[2];
    float x45 = (k & 1) ? a[5] : a[4];
    float x67 = (k & 1) ? a[7] : a[6];
    float y0  = (k & 2) ? x23 : x01;
    float y1  = (k & 2) ? x67 : x45;
    return (k & 4) ? y1 : y0;
}

// 4 cuts per warp: lane = 8*g + s; group g handles cut warp*4+g.
// STRIDED bin ownership: lane s owns bins {8k+s, k=0..7} -> coalesced 32B
// group loads (1-2 sectors per group per LDG instead of 32-sector strides).
__global__ __launch_bounds__(256)
void rqs_logdet4c_kernel(const float* __restrict__ value,
                         const float* __restrict__ delta_spline,
                         const int*   __restrict__ genes_oi,
                         const int*   __restrict__ local_gene_ix,
                         const float* __restrict__ spline_weight,
                         float*       __restrict__ out,
                         int n)
{
    const unsigned FULL = 0xffffffffu;
    const float WINDOW_A      = -10000.0f;
    const float INV_AB        = 1.0f / 20000.0f;
    const float MBW           = 0.001f;
    const float MBH           = 0.001f;
    const float MDER          = 0.001f;
    const float DEFAULT_INIT  = 0.53974366f;                 // log(exp(0.999)-1)
    const float OUT_CONST     = -0.69314718f - 9.90348755f;  // LOG_HALF - LOG_AB
    const float cH            = 1.0f - MBH * KB;             // 0.936
    const float cW            = 1.0f - MBW * KB;

    const int lane = threadIdx.x & 31;
    const int g    = lane >> 3;
    const int s    = lane & 7;
    int warp = (int)((blockIdx.x * (unsigned)blockDim.x + threadIdx.x) >> 5);
    long long cut_base = (long long)warp * 4;
    if (cut_base >= n) return;                 // whole-warp uniform exit
    long long cutl = cut_base + g;
    bool active = (cutl < n);
    int cut = active ? (int)cutl : (n - 1);

    const float* ds = delta_spline + (long long)cut * NSPL;
    int gene = genes_oi[local_gene_ix[cut]];
    const float* sw = spline_weight + (long long)gene * NSPL;

    // ---- coalesced stream: round k reads cols 8k+s (w) and 64+8k+s (h) ----
    float uwv[8], ehv[8];
    #pragma unroll
    for (int k = 0; k < 8; ++k) {
        int j = 8 * k + s;
        uwv[k] = ds[j]      + sw[j];
        ehv[k] = __expf(ds[KB + j] + sw[KB + j]);
    }

    // widths total (per-lane accumulate, then width-8 butterfly)
    float Swl = 0.0f;
    #pragma unroll
    for (int k = 0; k < 8; ++k) Swl += __expf(uwv[k]);
    #pragma unroll
    for (int o = 4; o; o >>= 1) Swl += __shfl_xor_sync(FULL, Swl, o, 8);

    // heights: 8 rounds of width-8 inclusive scan with carry
    // cum[k] on lane s = inclusive cumexp at bin 8k+s
    float cum[8];
    float carry = 0.0f;
    #pragma unroll
    for (int k = 0; k < 8; ++k) {
        float isc = ehv[k];
        #pragma unroll
        for (int o = 1; o < 8; o <<= 1) {
            float u = __shfl_up_sync(FULL, isc, o, 8);
            if (s >= o) isc += u;
        }
        cum[k] = carry + isc;
        carry = __shfl_sync(FULL, cum[k], 7, 8);
    }
    float Sh = carry;

    // ---- x ----
    float v  = value[cut];
    float x  = ((v - WINDOW_A) * INV_AB - 0.5f) * 2.0f;
    bool inside = (x >= -1.0f) && (x <= 1.0f);
    float xc = fminf(fmaxf(x, -1.0f), 1.0f);

    // ---- bin search: count bins j with cum[j] <= R(j) ----
    float invSh = __fdividef(1.0f, Sh);
    float ShocH = Sh * (1.0f / cH);
    float step8 = 8.0f * MBH * ShocH;
    float R = (fmaf(xc, 0.5f, 0.5f) - (float)(s + 1) * MBH) * ShocH;
    int cnt = 0;
    #pragma unroll
    for (int k = 0; k < 8; ++k) {
        cnt += (cum[k] <= R);
        R -= step8;
    }
    #pragma unroll
    for (int o = 4; o; o >>= 1) cnt += __shfl_xor_sync(FULL, cnt, o, 8);
    int idx = min(cnt, 63);                        // group-uniform

    // ---- register gathers at idx (k1,s1) and idx-1 (k0,s0) ----
    int k1 = idx >> 3, s1 = idx & 7;
    float cumIdx = __shfl_sync(FULL, sel8(cum, k1), s1, 8);
    int p  = idx - 1;
    int k0 = (p >= 0) ? (p >> 3) : 0;
    int s0 = p & 7;                                // p=-1 -> 7, value overridden
    float c0 = __shfl_sync(FULL, sel8(cum, k0), s0, 8);
    if (idx == 0) c0 = 0.0f;
    float eh_g = cumIdx - c0;                      // exp(uh[idx])
    float ew_g = __expf(__shfl_sync(FULL, sel8(uwv, k1), s1, 8));

    // ---- derivatives: only 2 scattered loads (ud region never streamed) ----
    int i0 = max(idx - 1, 0);
    int i1 = min(idx, 62);
    float u0 = ds[2 * KB + i0] + sw[2 * KB + i0];
    float u1 = ds[2 * KB + i1] + sw[2 * KB + i1];
    if (idx == 0)  u0 = DEFAULT_INIT;
    if (idx == 63) u1 = DEFAULT_INIT;
    float d0 = MDER + softplus_f(u0);
    float d1 = MDER + softplus_f(u1);

    // ---- spline quantities at idx ----
    float h_sm = fmaf(cH * invSh, eh_g, MBH);
    float w_sm = fmaf(cW, __fdividef(ew_g, Swl), MBW);
    float in_h = 2.0f * h_sm;
    float dlt  = __fdividef(h_sm, w_sm);
    float in_ch = fmaf(2.0f, fmaf(cH * invSh, c0, (float)idx * MBH), -1.0f);

    // ---- rational-quadratic inverse, logabsdet only ----
    float dy = xc - in_ch;
    float sc = d0 + d1 - 2.0f * dlt;
    float a  = dy * sc + in_h * (dlt - d0);
    float b  = in_h * d0 - dy * sc;
    float c  = -dlt * dy;
    float disc = b * b - 4.0f * a * c;
    float root = __fdividef(2.0f * c, -b - sqrtf(fmaxf(disc, 0.0f)));
    float tom  = root * (1.0f - root);
    float denom = dlt + sc * tom;
    float omr  = 1.0f - root;
    float deriv_num = dlt * dlt * (d1 * root * root + 2.0f * dlt * tom + d0 * omr * omr);
    float logabsdet = -(__logf(deriv_num) - 2.0f * __logf(denom));

    float res = OUT_CONST + (inside ? logabsdet : 0.0f);
    if (s == 0 && active) out[cut] = res;          // 4 consecutive floats / warp
}

extern "C" void kernel_launch(void* const* d_in, const int* in_sizes, int n_in,
                              void* d_out, int out_size) {
    const float* value         = (const float*)d_in[0];
    const float* delta_spline  = (const float*)d_in[1];
    const int*   genes_oi      = (const int*)d_in[2];
    const int*   local_gene_ix = (const int*)d_in[3];
    const float* spline_weight = (const float*)d_in[4];
    float* out = (float*)d_out;
    int n = in_sizes[0];                      // N_CUTS
    int blocks = (n + 31) / 32;               // 32 cuts per 256-thread block
    rqs_logdet4c_kernel<<<blocks, 256>>>(value, delta_spline, genes_oi,
                                         local_gene_ix, spline_weight, out, n);
}